// round 11
// baseline (speedup 1.0000x reference)
#include <cuda_runtime.h>
#include <cuda_fp16.h>
#include <math.h>
#include <stdint.h>

#define HH    512
#define VSS   32000
#define ROWS  2048
#define NCB   250
#define AROWS 2176    // 2048 rows + null row (2048) + zero pad to 17*128

typedef unsigned long long u64;
typedef unsigned int u32;

// ---------------- static device scratch ----------------
__device__ __align__(16) float g_Ae[AROWS * HH];   // tanh states + null + pad
__device__ __align__(16) float g_nullLogits[VSS];
__device__ float g_nullPart[NCB];
__device__ float g_nullSum;
__device__ __align__(16) float g_partE[NCB * ROWS];
__device__ __align__(16) float g_partT[NCB * ROWS];
__device__ __align__(16) float g_emGath[ROWS * 64];
__device__ __align__(16) float g_tgtLogit[ROWS];
__device__ u64 g_argmax[ROWS];

// ---------------- helpers ----------------
__device__ __forceinline__ u64 key64(float x, int col) {
    unsigned u = __float_as_uint(x);
    u = (u & 0x80000000u) ? ~u : (u | 0x80000000u);
    return ((u64)u << 32) | (unsigned)(~(unsigned)col);
}
__device__ __forceinline__ void ffma2(u64& d, u64 a, u64 b) {
    asm("fma.rn.f32x2 %0, %1, %2, %0;" : "+l"(d) : "l"(a), "l"(b));
}
__device__ __forceinline__ u64 pk2(float x) {
    u64 r; asm("mov.b64 %0, {%1, %1};" : "=l"(r) : "f"(x)); return r;
}
__device__ __forceinline__ float2 up2(u64 v) {
    float2 r; asm("mov.b64 {%0, %1}, %2;" : "=f"(r.x), "=f"(r.y) : "l"(v)); return r;
}
__device__ __forceinline__ void hmma(float* d, const u32* a, const u32* b) {
    asm volatile("mma.sync.aligned.m16n8k16.row.col.f32.f16.f16.f32 "
                 "{%0,%1,%2,%3},{%4,%5,%6,%7},{%8,%9},{%0,%1,%2,%3};"
                 : "+f"(d[0]), "+f"(d[1]), "+f"(d[2]), "+f"(d[3])
                 : "r"(a[0]), "r"(a[1]), "r"(a[2]), "r"(a[3]), "r"(b[0]), "r"(b[1]));
}
__device__ __forceinline__ u32 packh2(__half a, __half b) {
    __half2 t = __halves2half2(a, b);
    return *(const u32*)&t;
}
__device__ __forceinline__ void split2(float x, float y, u32& hi, u32& lo) {
    __half hx = __float2half_rn(x), hy = __float2half_rn(y);
    hi = packh2(hx, hy);
    lo = packh2(__float2half_rn(x - __half2float(hx)),
                __float2half_rn(y - __half2float(hy)));
}

// ---------------- init: argmax reset + zero A pad rows ----------------
__global__ void k_init() {
    int i = blockIdx.x * blockDim.x + threadIdx.x;
    if (i < ROWS) g_argmax[i] = 0ull;
    if (i < 127 * HH) g_Ae[(2049) * HH + i] = 0.f;
}

// null state -> row 2048 of g_Ae
__global__ void k_tsn(const float* __restrict__ yn, const float* __restrict__ W,
                      const float* __restrict__ bias) {
    __shared__ float y[HH];
    int t = threadIdx.x;
    y[t] = yn[t];
    __syncthreads();
    float acc = bias[t];
#pragma unroll 8
    for (int k = 0; k < HH; k++) acc += y[k] * W[k * HH + t];
    g_Ae[ROWS * HH + t] = tanhf(acc);
}

// ts = tanh(y_hidden @ W_em + b_em) -> g_Ae rows 0..2047  (round-1 proven FFMA2)
__global__ void __launch_bounds__(256) k_ts(const float* __restrict__ A,
                                            const float* __restrict__ Bmat,
                                            const float* __restrict__ bias) {
    __shared__ __align__(16) float As[16][132];
    __shared__ __align__(16) float Bs[16][128];
    const int tid = threadIdx.x;
    const int tx = tid & 15, ty = tid >> 4;
    const int c0 = blockIdx.x * 128;
    const int r0 = blockIdx.y * 128;

    u64 acc[8][4];
#pragma unroll
    for (int i = 0; i < 8; i++)
#pragma unroll
        for (int q = 0; q < 4; q++) acc[i][q] = 0ull;

    float4 pa[2], pb[2];
#pragma unroll
    for (int u = 0; u < 2; u++) {
        int v = tid + u * 256;
        pa[u] = *(const float4*)(A + (size_t)(r0 + (v >> 2)) * HH + ((v & 3) << 2));
        pb[u] = *(const float4*)(Bmat + (size_t)(v >> 5) * HH + c0 + ((v & 31) << 2));
    }
    for (int kt = 0; kt < 32; kt++) {
        __syncthreads();
#pragma unroll
        for (int u = 0; u < 2; u++) {
            int v = tid + u * 256;
            int rr = v >> 2, k4 = (v & 3) << 2;
            As[k4 + 0][rr] = pa[u].x; As[k4 + 1][rr] = pa[u].y;
            As[k4 + 2][rr] = pa[u].z; As[k4 + 3][rr] = pa[u].w;
            *(float4*)&Bs[v >> 5][(v & 31) << 2] = pb[u];
        }
        __syncthreads();
        if (kt + 1 < 32) {
            int kb = (kt + 1) * 16;
#pragma unroll
            for (int u = 0; u < 2; u++) {
                int v = tid + u * 256;
                pa[u] = *(const float4*)(A + (size_t)(r0 + (v >> 2)) * HH + kb + ((v & 3) << 2));
                pb[u] = *(const float4*)(Bmat + (size_t)(kb + (v >> 5)) * HH + c0 + ((v & 31) << 2));
            }
        }
#pragma unroll
        for (int kk = 0; kk < 16; kk++) {
            float4 a0 = *(const float4*)&As[kk][ty * 4];
            float4 a1 = *(const float4*)&As[kk][64 + ty * 4];
            ulonglong2 b0 = *(const ulonglong2*)&Bs[kk][tx * 4];
            ulonglong2 b1 = *(const ulonglong2*)&Bs[kk][64 + tx * 4];
            float av[8] = {a0.x, a0.y, a0.z, a0.w, a1.x, a1.y, a1.z, a1.w};
#pragma unroll
            for (int i = 0; i < 8; i++) {
                u64 ap = pk2(av[i]);
                ffma2(acc[i][0], ap, b0.x); ffma2(acc[i][1], ap, b0.y);
                ffma2(acc[i][2], ap, b1.x); ffma2(acc[i][3], ap, b1.y);
            }
        }
    }
#pragma unroll
    for (int i = 0; i < 8; i++) {
        int r = r0 + (i >> 2) * 64 + ty * 4 + (i & 3);
#pragma unroll
        for (int q = 0; q < 4; q++) {
            float2 p = up2(acc[i][q]);
            int c = c0 + (q >> 1) * 64 + tx * 4 + (q & 1) * 2;
            g_Ae[(size_t)r * HH + c]     = tanhf(p.x + bias[c]);
            g_Ae[(size_t)r * HH + c + 1] = tanhf(p.y + bias[c + 1]);
        }
    }
}

// ======== HMMA fused GEMM: half-plane staging, double-buffered ========
// per-stage smem (u32): Ah[128*20], Al[128*20], Bh[16*136], Bl[16*136] = 9472 u32
#define APAD 20
#define BPAD 136
#define STG_U32 9472

template <int TMODE>
__global__ void __launch_bounds__(256) hm_gemm(const float* __restrict__ Ag,
                                               const float* __restrict__ Bg,
                                               const float* __restrict__ bias,
                                               const int* __restrict__ gidx) {
    extern __shared__ char dsm[];
    __shared__ float s_bias[128];
    __shared__ int   s_idx[128];

    const int tid = threadIdx.x;
    const int wid = tid >> 5, lane = tid & 31;
    const int wm = wid & 1, wn = wid >> 1;    // 2 x 4 warp grid
    const int lq = lane >> 2;                 // groupID 0..7
    const int lm = lane & 3;
    const int r0 = blockIdx.x * 128;
    const int c0 = blockIdx.y * 128;
    const bool nullblk = (TMODE == 0) && (blockIdx.x == 16);

    const float* Ap = (TMODE == 0) ? (const float*)g_Ae : Ag;

    if (tid < 128) {
        s_bias[tid] = bias[c0 + tid];
        if (!nullblk) s_idx[tid] = gidx[r0 + tid];
    }

    float acc[4][4][4];
#pragma unroll
    for (int a = 0; a < 4; a++)
#pragma unroll
        for (int b = 0; b < 4; b++)
#pragma unroll
            for (int c = 0; c < 4; c++) acc[a][b][c] = 0.f;

    float4 pa[4], pb0[2], pb1[2];
#define LDGC(kc) do { \
    _Pragma("unroll") for (int u = 0; u < 4; u++) { \
        int v = tid + u * 256; \
        int ar = v >> 3, aq = (v & 7) * 4; \
        pa[u] = *(const float4*)(Ap + (size_t)(r0 + ar) * HH + (kc) * 32 + aq); \
    } \
    _Pragma("unroll") for (int u = 0; u < 2; u++) { \
        int v = tid + u * 256; \
        int k2 = v >> 5, n4 = (v & 31) * 4; \
        pb0[u] = *(const float4*)(Bg + (size_t)((kc) * 32 + 2 * k2) * VSS + c0 + n4); \
        pb1[u] = *(const float4*)(Bg + (size_t)((kc) * 32 + 2 * k2 + 1) * VSS + c0 + n4); \
    } } while (0)

#define STSC(buf) do { \
    u32* Ah_s = (buf); u32* Al_s = Ah_s + 128 * APAD; \
    u32* Bh_s = Al_s + 128 * APAD; u32* Bl_s = Bh_s + 16 * BPAD; \
    _Pragma("unroll") for (int u = 0; u < 4; u++) { \
        int v = tid + u * 256; \
        int ar = v >> 3, q = (v & 7) * 2; \
        u32 h0, l0, h1, l1; \
        split2(pa[u].x, pa[u].y, h0, l0); \
        split2(pa[u].z, pa[u].w, h1, l1); \
        int base = ar * APAD + q; \
        Ah_s[base] = h0; Ah_s[base + 1] = h1; \
        Al_s[base] = l0; Al_s[base + 1] = l1; \
    } \
    _Pragma("unroll") for (int u = 0; u < 2; u++) { \
        int v = tid + u * 256; \
        int k2 = v >> 5, n4 = (v & 31) * 4; \
        int base = k2 * BPAD + n4; \
        u32 h, l; \
        split2(pb0[u].x, pb1[u].x, h, l); Bh_s[base + 0] = h; Bl_s[base + 0] = l; \
        split2(pb0[u].y, pb1[u].y, h, l); Bh_s[base + 1] = h; Bl_s[base + 1] = l; \
        split2(pb0[u].z, pb1[u].z, h, l); Bh_s[base + 2] = h; Bl_s[base + 2] = l; \
        split2(pb0[u].w, pb1[u].w, h, l); Bh_s[base + 3] = h; Bl_s[base + 3] = l; \
    } } while (0)

    u32* stg0 = (u32*)dsm;
    u32* stg1 = stg0 + STG_U32;

    LDGC(0);
    STSC(stg0);
    __syncthreads();

    for (int kc = 0; kc < 16; kc++) {
        if (kc + 1 < 16) LDGC(kc + 1);

        // --- compute chunk kc from buf[kc&1] ---
        u32* cur = (kc & 1) ? stg1 : stg0;
        u32* Ah_c = cur;
        u32* Al_c = Ah_c + 128 * APAD;
        u32* Bh_c = Al_c + 128 * APAD;
        u32* Bl_c = Bh_c + 16 * BPAD;
#pragma unroll
        for (int kk = 0; kk < 2; kk++) {
            u32 ah[4][4], al[4][4], bh[4][2], bl[4][2];
#pragma unroll
            for (int mt = 0; mt < 4; mt++) {
                int rA = wm * 64 + mt * 16 + lq;
#pragma unroll
                for (int rr = 0; rr < 4; rr++) {
                    int row = rA + 8 * (rr & 1);
                    int col = kk * 8 + lm + 4 * (rr >> 1);
                    ah[mt][rr] = Ah_c[row * APAD + col];
                    al[mt][rr] = Al_c[row * APAD + col];
                }
            }
#pragma unroll
            for (int nt = 0; nt < 4; nt++) {
                int nB = wn * 32 + nt * 8 + lq;
#pragma unroll
                for (int rr = 0; rr < 2; rr++) {
                    int p = kk * 8 + lm + 4 * rr;
                    bh[nt][rr] = Bh_c[p * BPAD + nB];
                    bl[nt][rr] = Bl_c[p * BPAD + nB];
                }
            }
#pragma unroll
            for (int mt = 0; mt < 4; mt++)
#pragma unroll
                for (int nt = 0; nt < 4; nt++)
                    hmma(acc[mt][nt], ah[mt], bh[nt]);
#pragma unroll
            for (int mt = 0; mt < 4; mt++)
#pragma unroll
                for (int nt = 0; nt < 4; nt++)
                    hmma(acc[mt][nt], al[mt], bh[nt]);
#pragma unroll
            for (int mt = 0; mt < 4; mt++)
#pragma unroll
                for (int nt = 0; nt < 4; nt++)
                    hmma(acc[mt][nt], ah[mt], bl[nt]);
        }

        if (kc + 1 < 16) STSC((kc & 1) ? stg0 : stg1);
        __syncthreads();
    }
#undef LDGC
#undef STSC

    // ---- epilogue (proven) ----
    float* slog = (float*)dsm;   // [128][132]
#pragma unroll
    for (int mt = 0; mt < 4; mt++)
#pragma unroll
        for (int nt = 0; nt < 4; nt++)
#pragma unroll
            for (int rg = 0; rg < 4; rg++) {
                int col = wn * 32 + nt * 8 + (lane & 3) * 2 + (rg & 1);
                int row = wm * 64 + mt * 16 + (lane >> 2) + 8 * (rg >> 1);
                slog[row * 132 + col] = acc[mt][nt][rg] + s_bias[col];
            }
    __syncthreads();

    if (nullblk) {
        if (tid < 128) g_nullLogits[c0 + tid] = slog[tid];
        if (tid == 0) {
            float esum = 0.f;
            for (int c = 0; c < 128; c++) esum += __expf(slog[c]);
            g_nullPart[blockIdx.y] = esum;
        }
        return;
    }

    if (tid < 128) {
        const float* rowp = slog + tid * 132;
        float esum = 0.f;
        u64 kmax = 0ull;
        for (int c = 0; c < 128; c++) {
            float v = rowp[c];
            esum += __expf(v);
            if (TMODE == 1) {
                u64 kk = key64(v, c0 + c);
                if (kk > kmax) kmax = kk;
            }
        }
        if (TMODE == 0) {
            g_partE[(size_t)blockIdx.y * ROWS + r0 + tid] = esum;
            int g = tid >> 6;
            for (int j = 0; j < 64; j++) {
                int c = s_idx[g * 64 + j] - c0;
                if (c >= 0 && c < 128)
                    g_emGath[(size_t)(r0 + tid) * 64 + j] = rowp[c];
            }
        } else {
            g_partT[(size_t)blockIdx.y * ROWS + r0 + tid] = esum;
            atomicMax(&g_argmax[r0 + tid], kmax);
            int c = s_idx[tid] - c0;
            if (c >= 0 && c < 128) g_tgtLogit[r0 + tid] = rowp[c];
        }
    }
}

// ---------------- null sum reduce + pack ----------------
__global__ void k_nullred() {
    __shared__ float red[128];
    int t = threadIdx.x;
    float s = 0.f;
    for (int i = t; i < NCB; i += 128) s += g_nullPart[i];
    red[t] = s;
    __syncthreads();
    for (int st = 64; st > 0; st >>= 1) {
        if (t < st) red[t] += red[t + st];
        __syncthreads();
    }
    if (t == 0) g_nullSum = red[0];
}

__global__ void k_pack(const int* __restrict__ sources, const int* __restrict__ tlen,
                       float* __restrict__ out) {
    int row = blockIdx.x * 128 + threadIdx.x;
    int b = row >> 6, t = row & 63;
    float sE = 0.f, sT = 0.f;
#pragma unroll 10
    for (int cb = 0; cb < NCB; cb++) {
        sE += g_partE[(size_t)cb * ROWS + row];
        sT += g_partT[(size_t)cb * ROWS + row];
    }
    float invE = 1.f / sE;
    float ns = 1.f / g_nullSum;
    size_t eb = (size_t)b * 8192;
    for (int j = 0; j < 64; j++)
        out[eb + t * 64 + j] = __expf(g_emGath[row * 64 + j]) * invE;
    for (int j = 0; j < 64; j++)
        out[eb + 4096 + t * 64 + j] = __expf(g_nullLogits[sources[b * 64 + j]]) * ns;
    float mask = (t < tlen[b]) ? 1.f : 0.f;
    float tl = g_tgtLogit[row];
    out[262144 + row] = mask * (__expf(tl) / sT);
    out[264192 + row] = mask * (tl - logf(sT));
    unsigned low = (unsigned)(g_argmax[row] & 0xFFFFFFFFull);
    out[266240 + row] = (float)(~low);
}

// ---------------- launch ----------------
extern "C" void kernel_launch(void* const* d_in, const int* in_sizes, int n_in,
                              void* d_out, int out_size) {
    const float* y_hidden  = (const float*)d_in[0];
    const float* y_null    = (const float*)d_in[1];
    const float* tgt_state = (const float*)d_in[2];
    const float* W_em      = (const float*)d_in[3];
    const float* b_em      = (const float*)d_in[4];
    const float* W_sv      = (const float*)d_in[5];
    const float* b_sv      = (const float*)d_in[6];
    const float* W_tv      = (const float*)d_in[7];
    const float* b_tv      = (const float*)d_in[8];
    const int*   sources   = (const int*)d_in[9];
    const int*   targets   = (const int*)d_in[10];
    const int*   tlen      = (const int*)d_in[11];
    float* out = (float*)d_out;

    const int DSMEM = 75776;   // 2 stages * 37888; slog (67584) fits
    cudaFuncSetAttribute(hm_gemm<0>, cudaFuncAttributeMaxDynamicSharedMemorySize, DSMEM);
    cudaFuncSetAttribute(hm_gemm<1>, cudaFuncAttributeMaxDynamicSharedMemorySize, DSMEM);

    k_init<<<256, 256>>>();
    k_tsn<<<1, 512>>>(y_null, W_em, b_em);
    k_ts<<<dim3(4, 16), 256>>>(y_hidden, W_em, b_em);
    hm_gemm<0><<<dim3(17, NCB), 256, DSMEM>>>(nullptr, W_sv, b_sv, sources);
    hm_gemm<1><<<dim3(16, NCB), 256, DSMEM>>>(tgt_state, W_tv, b_tv, targets);
    k_nullred<<<1, 128>>>();
    k_pack<<<16, 128>>>(sources, tlen, out);
}

// round 12
// speedup vs baseline: 1.1933x; 1.1933x over previous
#include <cuda_runtime.h>
#include <cuda_fp16.h>
#include <math.h>
#include <stdint.h>

#define HH    512
#define VSS   32000
#define ROWS  2048
#define NCB   250
#define AROWS 2176    // 2048 rows + null row (2048) + zero pad to 17*128

typedef unsigned long long u64;
typedef unsigned int u32;

// ---------------- static device scratch ----------------
__device__ __align__(16) float g_Ae[AROWS * HH];   // tanh states + null + pad
__device__ __align__(16) float g_nullLogits[VSS];
__device__ float g_nullPart[NCB];
__device__ float g_nullSum;
__device__ __align__(16) float g_partE[NCB * ROWS];
__device__ __align__(16) float g_partT[NCB * ROWS];
__device__ __align__(16) float g_emGath[ROWS * 64];
__device__ __align__(16) float g_tgtLogit[ROWS];
__device__ u64 g_argmax[ROWS];

// ---------------- helpers ----------------
__device__ __forceinline__ u64 key64(float x, int col) {
    unsigned u = __float_as_uint(x);
    u = (u & 0x80000000u) ? ~u : (u | 0x80000000u);
    return ((u64)u << 32) | (unsigned)(~(unsigned)col);
}
__device__ __forceinline__ void ffma2(u64& d, u64 a, u64 b) {
    asm("fma.rn.f32x2 %0, %1, %2, %0;" : "+l"(d) : "l"(a), "l"(b));
}
__device__ __forceinline__ u64 pk2(float x) {
    u64 r; asm("mov.b64 %0, {%1, %1};" : "=l"(r) : "f"(x)); return r;
}
__device__ __forceinline__ float2 up2(u64 v) {
    float2 r; asm("mov.b64 {%0, %1}, %2;" : "=f"(r.x), "=f"(r.y) : "l"(v)); return r;
}
__device__ __forceinline__ void hmma(float* d, const u32* a, const u32* b) {
    asm volatile("mma.sync.aligned.m16n8k16.row.col.f32.f16.f16.f32 "
                 "{%0,%1,%2,%3},{%4,%5,%6,%7},{%8,%9},{%0,%1,%2,%3};"
                 : "+f"(d[0]), "+f"(d[1]), "+f"(d[2]), "+f"(d[3])
                 : "r"(a[0]), "r"(a[1]), "r"(a[2]), "r"(a[3]), "r"(b[0]), "r"(b[1]));
}
__device__ __forceinline__ u32 packh2(__half a, __half b) {
    __half2 t = __halves2half2(a, b);
    return *(const u32*)&t;
}
__device__ __forceinline__ void split2(float x, float y, u32& hi, u32& lo) {
    __half hx = __float2half_rn(x), hy = __float2half_rn(y);
    hi = packh2(hx, hy);
    lo = packh2(__float2half_rn(x - __half2float(hx)),
                __float2half_rn(y - __half2float(hy)));
}

// ---------------- init: argmax reset + zero A pad rows ----------------
__global__ void k_init() {
    int i = blockIdx.x * blockDim.x + threadIdx.x;
    if (i < ROWS) g_argmax[i] = 0ull;
    if (i < 127 * HH) g_Ae[(2049) * HH + i] = 0.f;
}

// null state -> row 2048 of g_Ae
__global__ void k_tsn(const float* __restrict__ yn, const float* __restrict__ W,
                      const float* __restrict__ bias) {
    __shared__ float y[HH];
    int t = threadIdx.x;
    y[t] = yn[t];
    __syncthreads();
    float acc = bias[t];
#pragma unroll 8
    for (int k = 0; k < HH; k++) acc += y[k] * W[k * HH + t];
    g_Ae[ROWS * HH + t] = tanhf(acc);
}

// ts = tanh(y_hidden @ W_em + b_em) -> g_Ae rows 0..2047  (round-1 proven FFMA2)
__global__ void __launch_bounds__(256) k_ts(const float* __restrict__ A,
                                            const float* __restrict__ Bmat,
                                            const float* __restrict__ bias) {
    __shared__ __align__(16) float As[16][132];
    __shared__ __align__(16) float Bs[16][128];
    const int tid = threadIdx.x;
    const int tx = tid & 15, ty = tid >> 4;
    const int c0 = blockIdx.x * 128;
    const int r0 = blockIdx.y * 128;

    u64 acc[8][4];
#pragma unroll
    for (int i = 0; i < 8; i++)
#pragma unroll
        for (int q = 0; q < 4; q++) acc[i][q] = 0ull;

    float4 pa[2], pb[2];
#pragma unroll
    for (int u = 0; u < 2; u++) {
        int v = tid + u * 256;
        pa[u] = *(const float4*)(A + (size_t)(r0 + (v >> 2)) * HH + ((v & 3) << 2));
        pb[u] = *(const float4*)(Bmat + (size_t)(v >> 5) * HH + c0 + ((v & 31) << 2));
    }
    for (int kt = 0; kt < 32; kt++) {
        __syncthreads();
#pragma unroll
        for (int u = 0; u < 2; u++) {
            int v = tid + u * 256;
            int rr = v >> 2, k4 = (v & 3) << 2;
            As[k4 + 0][rr] = pa[u].x; As[k4 + 1][rr] = pa[u].y;
            As[k4 + 2][rr] = pa[u].z; As[k4 + 3][rr] = pa[u].w;
            *(float4*)&Bs[v >> 5][(v & 31) << 2] = pb[u];
        }
        __syncthreads();
        if (kt + 1 < 32) {
            int kb = (kt + 1) * 16;
#pragma unroll
            for (int u = 0; u < 2; u++) {
                int v = tid + u * 256;
                pa[u] = *(const float4*)(A + (size_t)(r0 + (v >> 2)) * HH + kb + ((v & 3) << 2));
                pb[u] = *(const float4*)(Bmat + (size_t)(kb + (v >> 5)) * HH + c0 + ((v & 31) << 2));
            }
        }
#pragma unroll
        for (int kk = 0; kk < 16; kk++) {
            float4 a0 = *(const float4*)&As[kk][ty * 4];
            float4 a1 = *(const float4*)&As[kk][64 + ty * 4];
            ulonglong2 b0 = *(const ulonglong2*)&Bs[kk][tx * 4];
            ulonglong2 b1 = *(const ulonglong2*)&Bs[kk][64 + tx * 4];
            float av[8] = {a0.x, a0.y, a0.z, a0.w, a1.x, a1.y, a1.z, a1.w};
#pragma unroll
            for (int i = 0; i < 8; i++) {
                u64 ap = pk2(av[i]);
                ffma2(acc[i][0], ap, b0.x); ffma2(acc[i][1], ap, b0.y);
                ffma2(acc[i][2], ap, b1.x); ffma2(acc[i][3], ap, b1.y);
            }
        }
    }
#pragma unroll
    for (int i = 0; i < 8; i++) {
        int r = r0 + (i >> 2) * 64 + ty * 4 + (i & 3);
#pragma unroll
        for (int q = 0; q < 4; q++) {
            float2 p = up2(acc[i][q]);
            int c = c0 + (q >> 1) * 64 + tx * 4 + (q & 1) * 2;
            g_Ae[(size_t)r * HH + c]     = tanhf(p.x + bias[c]);
            g_Ae[(size_t)r * HH + c + 1] = tanhf(p.y + bias[c + 1]);
        }
    }
}

// ======== HMMA fused GEMM: half-plane staging (round-10 layout), 2 CTA/SM ========
#define APAD 20
#define BPAD 136

template <int TMODE>
__global__ void __launch_bounds__(256, 2) hm_gemm(const float* __restrict__ Ag,
                                                  const float* __restrict__ Bg,
                                                  const float* __restrict__ bias,
                                                  const int* __restrict__ gidx) {
    extern __shared__ char dsm[];
    __shared__ float s_bias[128];
    __shared__ int   s_idx[128];

    u32* Ah_s = (u32*)dsm;            // 2560 u32
    u32* Al_s = Ah_s + 128 * APAD;    // 2560
    u32* Bh_s = Al_s + 128 * APAD;    // 2176
    u32* Bl_s = Bh_s + 16 * BPAD;     // 2176  (total 37888 B)

    const int tid = threadIdx.x;
    const int wid = tid >> 5, lane = tid & 31;
    const int wm = wid & 1, wn = wid >> 1;    // 2 x 4 warp grid
    const int lq = lane >> 2;                 // groupID 0..7
    const int lm = lane & 3;
    const int r0 = blockIdx.x * 128;
    const int c0 = blockIdx.y * 128;
    const bool nullblk = (TMODE == 0) && (blockIdx.x == 16);

    const float* Ap = (TMODE == 0) ? (const float*)g_Ae : Ag;

    if (tid < 128) {
        s_bias[tid] = bias[c0 + tid];
        if (!nullblk) s_idx[tid] = gidx[r0 + tid];
    }

    float acc[4][4][4];
#pragma unroll
    for (int a = 0; a < 4; a++)
#pragma unroll
        for (int b = 0; b < 4; b++)
#pragma unroll
            for (int c = 0; c < 4; c++) acc[a][b][c] = 0.f;

    for (int kc = 0; kc < 16; kc++) {
        __syncthreads();          // previous consume done
        // --- stage: LDG -> convert -> STS (no long-lived prefetch regs) ---
#pragma unroll
        for (int u = 0; u < 4; u++) {
            int v = tid + u * 256;
            int ar = v >> 3, aq = (v & 7) * 4;
            float4 va = *(const float4*)(Ap + (size_t)(r0 + ar) * HH + kc * 32 + aq);
            u32 h0, l0, h1, l1;
            split2(va.x, va.y, h0, l0);
            split2(va.z, va.w, h1, l1);
            int base = ar * APAD + (v & 7) * 2;
            Ah_s[base] = h0; Ah_s[base + 1] = h1;
            Al_s[base] = l0; Al_s[base + 1] = l1;
        }
#pragma unroll
        for (int u = 0; u < 2; u++) {
            int v = tid + u * 256;
            int k2 = v >> 5, n4 = (v & 31) * 4;
            float4 vb0 = *(const float4*)(Bg + (size_t)(kc * 32 + 2 * k2) * VSS + c0 + n4);
            float4 vb1 = *(const float4*)(Bg + (size_t)(kc * 32 + 2 * k2 + 1) * VSS + c0 + n4);
            int base = k2 * BPAD + n4;
            u32 h, l;
            split2(vb0.x, vb1.x, h, l); Bh_s[base + 0] = h; Bl_s[base + 0] = l;
            split2(vb0.y, vb1.y, h, l); Bh_s[base + 1] = h; Bl_s[base + 1] = l;
            split2(vb0.z, vb1.z, h, l); Bh_s[base + 2] = h; Bl_s[base + 2] = l;
            split2(vb0.w, vb1.w, h, l); Bh_s[base + 3] = h; Bl_s[base + 3] = l;
        }
        __syncthreads();          // tiles ready

        // --- pure LDS + HMMA, nt-innermost (only 4 B regs live) ---
#pragma unroll
        for (int kk = 0; kk < 2; kk++) {
            u32 ah[4][4], al[4][4];
#pragma unroll
            for (int mt = 0; mt < 4; mt++) {
                int rA = wm * 64 + mt * 16 + lq;
#pragma unroll
                for (int rr = 0; rr < 4; rr++) {
                    int row = rA + 8 * (rr & 1);
                    int col = kk * 8 + lm + 4 * (rr >> 1);
                    ah[mt][rr] = Ah_s[row * APAD + col];
                    al[mt][rr] = Al_s[row * APAD + col];
                }
            }
#pragma unroll
            for (int nt = 0; nt < 4; nt++) {
                int nB = wn * 32 + nt * 8 + lq;
                u32 bh[2], bl[2];
#pragma unroll
                for (int rr = 0; rr < 2; rr++) {
                    int p = kk * 8 + lm + 4 * rr;
                    bh[rr] = Bh_s[p * BPAD + nB];
                    bl[rr] = Bl_s[p * BPAD + nB];
                }
#pragma unroll
                for (int mt = 0; mt < 4; mt++) hmma(acc[mt][nt], ah[mt], bh);
#pragma unroll
                for (int mt = 0; mt < 4; mt++) hmma(acc[mt][nt], al[mt], bh);
#pragma unroll
                for (int mt = 0; mt < 4; mt++) hmma(acc[mt][nt], ah[mt], bl);
            }
        }
    }

    // ---- epilogue (proven) ----
    __syncthreads();
    float* slog = (float*)dsm;   // [128][132]
#pragma unroll
    for (int mt = 0; mt < 4; mt++)
#pragma unroll
        for (int nt = 0; nt < 4; nt++)
#pragma unroll
            for (int rg = 0; rg < 4; rg++) {
                int col = wn * 32 + nt * 8 + (lane & 3) * 2 + (rg & 1);
                int row = wm * 64 + mt * 16 + (lane >> 2) + 8 * (rg >> 1);
                slog[row * 132 + col] = acc[mt][nt][rg] + s_bias[col];
            }
    __syncthreads();

    if (nullblk) {
        if (tid < 128) g_nullLogits[c0 + tid] = slog[tid];
        if (tid == 0) {
            float esum = 0.f;
            for (int c = 0; c < 128; c++) esum += __expf(slog[c]);
            g_nullPart[blockIdx.y] = esum;
        }
        return;
    }

    if (tid < 128) {
        const float* rowp = slog + tid * 132;
        float esum = 0.f;
        u64 kmax = 0ull;
        for (int c = 0; c < 128; c++) {
            float v = rowp[c];
            esum += __expf(v);
            if (TMODE == 1) {
                u64 kk = key64(v, c0 + c);
                if (kk > kmax) kmax = kk;
            }
        }
        if (TMODE == 0) {
            g_partE[(size_t)blockIdx.y * ROWS + r0 + tid] = esum;
            int g = tid >> 6;
            for (int j = 0; j < 64; j++) {
                int c = s_idx[g * 64 + j] - c0;
                if (c >= 0 && c < 128)
                    g_emGath[(size_t)(r0 + tid) * 64 + j] = rowp[c];
            }
        } else {
            g_partT[(size_t)blockIdx.y * ROWS + r0 + tid] = esum;
            atomicMax(&g_argmax[r0 + tid], kmax);
            int c = s_idx[tid] - c0;
            if (c >= 0 && c < 128) g_tgtLogit[r0 + tid] = rowp[c];
        }
    }
}

// ---------------- null sum reduce + pack ----------------
__global__ void k_nullred() {
    __shared__ float red[128];
    int t = threadIdx.x;
    float s = 0.f;
    for (int i = t; i < NCB; i += 128) s += g_nullPart[i];
    red[t] = s;
    __syncthreads();
    for (int st = 64; st > 0; st >>= 1) {
        if (t < st) red[t] += red[t + st];
        __syncthreads();
    }
    if (t == 0) g_nullSum = red[0];
}

__global__ void k_pack(const int* __restrict__ sources, const int* __restrict__ tlen,
                       float* __restrict__ out) {
    int row = blockIdx.x * 128 + threadIdx.x;
    int b = row >> 6, t = row & 63;
    float sE = 0.f, sT = 0.f;
#pragma unroll 10
    for (int cb = 0; cb < NCB; cb++) {
        sE += g_partE[(size_t)cb * ROWS + row];
        sT += g_partT[(size_t)cb * ROWS + row];
    }
    float invE = 1.f / sE;
    float ns = 1.f / g_nullSum;
    size_t eb = (size_t)b * 8192;
    for (int j = 0; j < 64; j++)
        out[eb + t * 64 + j] = __expf(g_emGath[row * 64 + j]) * invE;
    for (int j = 0; j < 64; j++)
        out[eb + 4096 + t * 64 + j] = __expf(g_nullLogits[sources[b * 64 + j]]) * ns;
    float mask = (t < tlen[b]) ? 1.f : 0.f;
    float tl = g_tgtLogit[row];
    out[262144 + row] = mask * (__expf(tl) / sT);
    out[264192 + row] = mask * (tl - logf(sT));
    unsigned low = (unsigned)(g_argmax[row] & 0xFFFFFFFFull);
    out[266240 + row] = (float)(~low);
}

// ---------------- launch ----------------
extern "C" void kernel_launch(void* const* d_in, const int* in_sizes, int n_in,
                              void* d_out, int out_size) {
    const float* y_hidden  = (const float*)d_in[0];
    const float* y_null    = (const float*)d_in[1];
    const float* tgt_state = (const float*)d_in[2];
    const float* W_em      = (const float*)d_in[3];
    const float* b_em      = (const float*)d_in[4];
    const float* W_sv      = (const float*)d_in[5];
    const float* b_sv      = (const float*)d_in[6];
    const float* W_tv      = (const float*)d_in[7];
    const float* b_tv      = (const float*)d_in[8];
    const int*   sources   = (const int*)d_in[9];
    const int*   targets   = (const int*)d_in[10];
    const int*   tlen      = (const int*)d_in[11];
    float* out = (float*)d_out;

    const int DSMEM = 69632;   // max(planes 37888, slog 67584); x2 CTAs = 136KB < 228KB
    cudaFuncSetAttribute(hm_gemm<0>, cudaFuncAttributeMaxDynamicSharedMemorySize, DSMEM);
    cudaFuncSetAttribute(hm_gemm<1>, cudaFuncAttributeMaxDynamicSharedMemorySize, DSMEM);

    k_init<<<256, 256>>>();
    k_tsn<<<1, 512>>>(y_null, W_em, b_em);
    k_ts<<<dim3(4, 16), 256>>>(y_hidden, W_em, b_em);
    hm_gemm<0><<<dim3(17, NCB), 256, DSMEM>>>(nullptr, W_sv, b_sv, sources);
    hm_gemm<1><<<dim3(16, NCB), 256, DSMEM>>>(tgt_state, W_tv, b_tv, targets);
    k_nullred<<<1, 128>>>();
    k_pack<<<16, 128>>>(sources, tlen, out);
}